// round 15
// baseline (speedup 1.0000x reference)
#include <cuda_runtime.h>
#include <cstdint>

#define ZB   16384
#define NIN  127
#define NF   128
#define KOUT 128
#define DTS  2080
#define NNF  (NF * NF)
#define RPAIR 8256
#define RPAD  8320          // 65 * 128
#define NHALF  130          // allocated halves (incl. zero pad)
#define NRUN   129          // halves actually processed

// Scratch (device globals)
__device__ __align__(16) float    g_M[KOUT * NNF];              // 8 MB tf32 W@T
__device__ __align__(16) float    g_B[NHALF * 128 * 64];        // packed sym M, permuted
__device__ __align__(16) uint32_t g_pair[RPAD];                 // i | (j<<16)

__device__ __forceinline__ uint32_t f2tf32(float x) {
    uint32_t r;
    asm("cvt.rna.tf32.f32 %0, %1;" : "=r"(r) : "f"(x));
    return r;
}

__device__ __forceinline__ void mma_tf32(float c[4], const uint32_t a[4], const uint32_t b[2]) {
    asm volatile(
        "mma.sync.aligned.m16n8k8.row.col.f32.tf32.tf32.f32 "
        "{%0,%1,%2,%3}, {%4,%5,%6,%7}, {%8,%9}, {%0,%1,%2,%3};"
        : "+f"(c[0]), "+f"(c[1]), "+f"(c[2]), "+f"(c[3])
        : "r"(a[0]), "r"(a[1]), "r"(a[2]), "r"(a[3]), "r"(b[0]), "r"(b[1]));
}

#define NB_SYNC(id)   asm volatile("bar.sync %0, 512;"   :: "r"(id) : "memory")
#define NB_ARRIVE(id) asm volatile("bar.arrive %0, 512;" :: "r"(id) : "memory")

// ---------------------------------------------------------------------------
// Kernel 1 (v3): M = W @ T.  512 threads / 16 warps, warp tile 32m x 32n.
// Fully async double-buffered staging: W [128m][36] and T row-major [32t][132n]
// both filled with 16B cp.async (4 ops/thread/chunk). B frags read from the
// [t][132] layout (<=2-way conflicts); W frags on proven CF stride-36.
// ---------------------------------------------------------------------------
#define S1_WBUF 4608                       // 128*36 words
#define S1_TBUF 4224                       // 32*132 words
#define S1_SMEM ((2 * S1_WBUF + 2 * S1_TBUF) * 4)   // 70656 B

__global__ void __launch_bounds__(512, 1) stage1_kernel(
        const float* __restrict__ W, const float* __restrict__ T) {
    extern __shared__ float s1[];
    float* Wb[2] = { s1, s1 + S1_WBUF };
    float* Tb[2] = { s1 + 2 * S1_WBUF, s1 + 2 * S1_WBUF + S1_TBUF };

    const int tid  = threadIdx.x;
    const int lane = tid & 31;
    const int warp = tid >> 5;
    const int gid  = lane >> 2;
    const int tig  = lane & 3;
    const int wm   = warp >> 2;        // 0..3 (m)
    const int wn   = warp & 3;         // 0..3 (n)
    const int colbase = blockIdx.x * 128;

    float acc[2][4][4];
#pragma unroll
    for (int mf = 0; mf < 2; mf++)
#pragma unroll
        for (int nf = 0; nf < 4; nf++)
#pragma unroll
            for (int q = 0; q < 4; q++) acc[mf][nf][q] = 0.0f;

    auto prefetch = [&](int c) {
        const int p = c & 1;
        const int kk = c * 32;
        // W tile: 1024 x 16B chunks (2 per thread)
#pragma unroll
        for (int t = 0; t < 2; t++) {
            int cc = tid + 512 * t;
            int m = cc >> 3, kg = cc & 7;
            uint32_t dst = (uint32_t)__cvta_generic_to_shared(Wb[p] + m * 36 + kg * 4);
            asm volatile("cp.async.ca.shared.global [%0], [%1], 16;"
                         :: "r"(dst), "l"(W + (size_t)m * DTS + kk + kg * 4));
        }
        // T tile row-major: 1024 x 16B chunks (2 per thread)
#pragma unroll
        for (int t = 0; t < 2; t++) {
            int cc = tid + 512 * t;
            int tt = cc >> 5, n4 = cc & 31;
            uint32_t dst = (uint32_t)__cvta_generic_to_shared(Tb[p] + tt * 132 + n4 * 4);
            asm volatile("cp.async.ca.shared.global [%0], [%1], 16;"
                         :: "r"(dst), "l"(T + (size_t)(kk + tt) * NNF + colbase + n4 * 4));
        }
        asm volatile("cp.async.commit_group;" ::: "memory");
    };

    prefetch(0);

    for (int c = 0; c < 65; ++c) {
        __syncthreads();                       // compute(c-1) done -> old buffer free
        if (c < 64) {
            prefetch(c + 1);
            asm volatile("cp.async.wait_group 1;" ::: "memory");   // chunk c landed
        } else {
            asm volatile("cp.async.wait_group 0;" ::: "memory");
        }
        __syncthreads();                       // visibility

        const float* Wsm = Wb[c & 1];
        const float* Tsm = Tb[c & 1];

#pragma unroll
        for (int ks = 0; ks < 4; ks++) {
            uint32_t breg[4][2];
#pragma unroll
            for (int nf = 0; nf < 4; nf++) {
                int n0 = wn * 32 + nf * 8 + gid;
                breg[nf][0] = f2tf32(Tsm[(ks * 8 + tig) * 132 + n0]);
                breg[nf][1] = f2tf32(Tsm[(ks * 8 + tig + 4) * 132 + n0]);
            }
#pragma unroll
            for (int mf = 0; mf < 2; mf++) {
                int r0 = wm * 32 + mf * 16 + gid;
                uint32_t a[4];
                a[0] = f2tf32(Wsm[r0 * 36 + ks * 8 + tig]);
                a[1] = f2tf32(Wsm[(r0 + 8) * 36 + ks * 8 + tig]);
                a[2] = f2tf32(Wsm[r0 * 36 + ks * 8 + tig + 4]);
                a[3] = f2tf32(Wsm[(r0 + 8) * 36 + ks * 8 + tig + 4]);
#pragma unroll
                for (int nf = 0; nf < 4; nf++)
                    mma_tf32(acc[mf][nf], a, breg[nf]);
            }
        }
    }

#pragma unroll
    for (int mf = 0; mf < 2; mf++) {
        int r0 = wm * 32 + mf * 16 + gid;
#pragma unroll
        for (int nf = 0; nf < 4; nf++) {
            int c0 = colbase + wn * 32 + nf * 8 + 2 * tig;
            g_M[r0 * NNF + c0]           = __uint_as_float(f2tf32(acc[mf][nf][0]));
            g_M[r0 * NNF + c0 + 1]       = __uint_as_float(f2tf32(acc[mf][nf][1]));
            g_M[(r0 + 8) * NNF + c0]     = __uint_as_float(f2tf32(acc[mf][nf][2]));
            g_M[(r0 + 8) * NNF + c0 + 1] = __uint_as_float(f2tf32(acc[mf][nf][3]));
        }
    }
}

// ---------------------------------------------------------------------------
// Pair table: r -> (i, j), i <= j, i-major
// ---------------------------------------------------------------------------
__global__ void build_pairs_kernel() {
    int i = blockIdx.x, j = threadIdx.x;
    if (j >= i) {
        int r = i * NF - (i * (i - 1)) / 2 + (j - i);
        g_pair[r] = (uint32_t)i | ((uint32_t)j << 16);
    }
    if (i == 0 && j < RPAD - RPAIR) g_pair[RPAIR + j] = 0;
}

// ---------------------------------------------------------------------------
// Pack (round-9 coalesced version): one block per k; smem tile; permuted write.
// ---------------------------------------------------------------------------
#define PACK_SMEM (128 * 129 * 4)   // 66048 B

__global__ void __launch_bounds__(256, 1) pack_kernel() {
    extern __shared__ float tile[];    // [128][129]
    const int k   = blockIdx.x;
    const int tid = threadIdx.x;
    const float* Mk = g_M + (size_t)k * NNF;

#pragma unroll
    for (int e = tid; e < NNF; e += 256) {
        int i = e >> 7, j = e & 127;
        tile[i * 129 + j] = Mk[e];
    }
    __syncthreads();

    for (int r = tid; r < RPAIR; r += 256) {
        uint32_t p = g_pair[r];
        int i = p & 0xFFFF, j = p >> 16;
        float v = tile[i * 129 + j];
        if (i != j) v += tile[j * 129 + i];
        int h  = r >> 6, rr = r & 63;
        int ks = rr >> 3, pos = rr & 7;
        int tg = pos & 3, b = pos >> 2;
        int w = (ks >> 1) * 16 + tg * 4 + 2 * (ks & 1) + b;
        g_B[(size_t)(h * 128 + k) * 64 + w] = __uint_as_float(f2tf32(v));
    }
}

// ---------------------------------------------------------------------------
// Stage 2: warp-specialized (confirmed config, verbatim), 512 threads.
// Warps 0-7: consumers (32z x 64k). Warps 8-15: producers. NRUN=129 halves.
// ---------------------------------------------------------------------------
#define FSTRF 129
#define BSTR  80
#define FSM_WORDS  (128 * FSTRF)          // 16512
#define AH_WORDS   8192
#define BH_WORDS   (128 * BSTR)           // 10240
#define S2_SMEM ((FSM_WORDS + 2 * AH_WORDS + 2 * BH_WORDS) * 4)  // 213504 B

__global__ void __launch_bounds__(512, 1) stage2_kernel(
        const float* __restrict__ feat, float* __restrict__ out) {
    extern __shared__ float sm[];
    float* fsm = sm;
    float* Abuf[2] = { sm + FSM_WORDS, sm + FSM_WORDS + AH_WORDS };
    float* Bbuf[2] = { sm + FSM_WORDS + 2 * AH_WORDS,
                       sm + FSM_WORDS + 2 * AH_WORDS + BH_WORDS };

    const int tid  = threadIdx.x;
    const int lane = tid & 31;
    const int warp = tid >> 5;
    const int gid  = lane >> 2;
    const int tig  = lane & 3;
    const int zbase = blockIdx.x * 128;

    for (int e = tid; e < 128 * 128; e += 512) {
        int z = e >> 7, c = e & 127;
        fsm[z * FSTRF + c] =
            (c == 0) ? 1.0f : feat[(size_t)(zbase + z) * NIN + (c - 1)];
    }
    __syncthreads();

    if (warp >= 8) {
        // ===================== PRODUCER (8 warps) =====================
        const int ptid = tid - 256;
        const int pw   = warp - 8;

        for (int h = 0; h < NRUN; ++h) {
            const int p = h & 1;
            if (h >= 2) NB_SYNC(3 + p);

            {
                float* buf = Bbuf[p];
                const float* src = g_B + (size_t)h * 8192;
#pragma unroll
                for (int t = 0; t < 8; t++) {
                    int cc = ptid + 256 * t;
                    int k = cc >> 4, grp = cc & 15;
                    uint32_t dst = (uint32_t)__cvta_generic_to_shared(buf + k * BSTR + grp * 4);
                    asm volatile("cp.async.cg.shared.global [%0], [%1], 16;"
                                 :: "r"(dst), "l"(src + k * 64 + grp * 4));
                }
                asm volatile("cp.async.commit_group;" ::: "memory");
            }

            {
                float* abuf = Abuf[p];
                const uint32_t* pb = g_pair + h * 64;
#pragma unroll
                for (int step = 0; step < 8; step++) {
                    int g = step * 8 + pw;
                    int mfq = g & 1;
                    int ksq = (g >> 1) & 7;
                    int wmq = g >> 4;
                    uint32_t p0 = __ldg(pb + ksq * 8 + tig);
                    uint32_t p1 = __ldg(pb + ksq * 8 + tig + 4);
                    int i0 = p0 & 0xFFFF, j0 = p0 >> 16;
                    int i1 = p1 & 0xFFFF, j1 = p1 >> 16;
                    const float* fz0 = fsm + (wmq * 32 + mfq * 16 + gid) * FSTRF;
                    const float* fz8 = fz0 + 8 * FSTRF;
                    uint32_t v0 = f2tf32(fz0[i0] * fz0[j0]);
                    uint32_t v1 = f2tf32(fz8[i0] * fz8[j0]);
                    uint32_t v2 = f2tf32(fz0[i1] * fz0[j1]);
                    uint32_t v3 = f2tf32(fz8[i1] * fz8[j1]);
                    uint32_t dst = (uint32_t)__cvta_generic_to_shared(
                        abuf + (size_t)g * 128 + lane * 4);
                    asm volatile("st.shared.v4.b32 [%0], {%1, %2, %3, %4};"
                                 :: "r"(dst), "r"(v0), "r"(v1), "r"(v2), "r"(v3));
                }
            }

            asm volatile("cp.async.wait_group 0;" ::: "memory");
            NB_ARRIVE(1 + p);
        }
    } else {
        // ===================== CONSUMER (8 warps, 32z x 64k) =====================
        const int wm = warp >> 1;
        const int wn = warp & 1;

        float acc[2][8][4];
#pragma unroll
        for (int mf = 0; mf < 2; mf++)
#pragma unroll
            for (int nf = 0; nf < 8; nf++)
#pragma unroll
                for (int q = 0; q < 4; q++) acc[mf][nf][q] = 0.0f;

        for (int h = 0; h < NRUN; ++h) {
            const int p = h & 1;
            NB_SYNC(1 + p);
            const float* abuf = Abuf[p];
            const float* bbuf = Bbuf[p];

#pragma unroll
            for (int klp = 0; klp < 4; klp++) {
                uint32_t a4[4][4];
#pragma unroll
                for (int s = 0; s < 2; s++)
#pragma unroll
                    for (int mf = 0; mf < 2; mf++) {
                        int g = wm * 16 + (2 * klp + s) * 2 + mf;
                        float4 v = *(const float4*)(abuf + (size_t)g * 128 + lane * 4);
                        a4[s * 2 + mf][0] = __float_as_uint(v.x);
                        a4[s * 2 + mf][1] = __float_as_uint(v.y);
                        a4[s * 2 + mf][2] = __float_as_uint(v.z);
                        a4[s * 2 + mf][3] = __float_as_uint(v.w);
                    }
#pragma unroll
                for (int nf = 0; nf < 8; nf++) {
                    int n0 = wn * 64 + nf * 8 + gid;
                    float4 v = *(const float4*)(bbuf + n0 * BSTR + klp * 16 + tig * 4);
                    uint32_t b0[2] = { __float_as_uint(v.x), __float_as_uint(v.y) };
                    uint32_t b1[2] = { __float_as_uint(v.z), __float_as_uint(v.w) };
#pragma unroll
                    for (int mf = 0; mf < 2; mf++) {
                        mma_tf32(acc[mf][nf], a4[0 * 2 + mf], b0);
                        mma_tf32(acc[mf][nf], a4[1 * 2 + mf], b1);
                    }
                }
            }
            NB_ARRIVE(3 + p);
        }

        // Epilogue
#pragma unroll
        for (int mf = 0; mf < 2; mf++) {
            int r0 = wm * 32 + mf * 16 + gid;
#pragma unroll
            for (int nf = 0; nf < 8; nf++) {
                int c0 = wn * 64 + nf * 8 + 2 * tig;
                out[(zbase + r0) * KOUT + c0]         = acc[mf][nf][0];
                out[(zbase + r0) * KOUT + c0 + 1]     = acc[mf][nf][1];
                out[(zbase + r0 + 8) * KOUT + c0]     = acc[mf][nf][2];
                out[(zbase + r0 + 8) * KOUT + c0 + 1] = acc[mf][nf][3];
            }
        }
    }
}

// ---------------------------------------------------------------------------
extern "C" void kernel_launch(void* const* d_in, const int* in_sizes, int n_in,
                              void* d_out, int out_size) {
    const float* feat = nullptr;
    const float* W    = nullptr;
    const float* T    = nullptr;
    for (int i = 0; i < n_in; i++) {
        if      (in_sizes[i] == ZB * NIN)   feat = (const float*)d_in[i];
        else if (in_sizes[i] == KOUT * DTS) W    = (const float*)d_in[i];
        else if (in_sizes[i] == DTS * NNF)  T    = (const float*)d_in[i];
    }
    float* out = (float*)d_out;

    cudaFuncSetAttribute(stage1_kernel,
                         cudaFuncAttributeMaxDynamicSharedMemorySize, S1_SMEM);
    cudaFuncSetAttribute(stage2_kernel,
                         cudaFuncAttributeMaxDynamicSharedMemorySize, S2_SMEM);
    cudaFuncSetAttribute(pack_kernel,
                         cudaFuncAttributeMaxDynamicSharedMemorySize, PACK_SMEM);

    build_pairs_kernel<<<128, 128>>>();
    stage1_kernel<<<128, 512, S1_SMEM>>>(W, T);
    pack_kernel<<<128, 256, PACK_SMEM>>>();
    stage2_kernel<<<128, 512, S2_SMEM>>>(feat, out);
}

// round 16
// speedup vs baseline: 1.0413x; 1.0413x over previous
#include <cuda_runtime.h>
#include <cstdint>

#define ZB   16384
#define NIN  127
#define NF   128
#define KOUT 128
#define DTS  2080
#define NNF  (NF * NF)
#define RPAIR 8256
#define RPAD  8320          // 65 * 128
#define NHALF  130          // allocated halves (incl. zero pad)
#define NRUN   129          // halves actually processed

// Scratch (device globals)
__device__ __align__(16) float    g_M[KOUT * NNF];              // 8 MB tf32 W@T
__device__ __align__(16) float    g_B[NHALF * 128 * 64];        // packed sym M, permuted
__device__ __align__(16) uint32_t g_pair[RPAD];                 // i | (j<<16)

__device__ __forceinline__ uint32_t f2tf32(float x) {
    uint32_t r;
    asm("cvt.rna.tf32.f32 %0, %1;" : "=r"(r) : "f"(x));
    return r;
}

__device__ __forceinline__ void mma_tf32(float c[4], const uint32_t a[4], const uint32_t b[2]) {
    asm volatile(
        "mma.sync.aligned.m16n8k8.row.col.f32.tf32.tf32.f32 "
        "{%0,%1,%2,%3}, {%4,%5,%6,%7}, {%8,%9}, {%0,%1,%2,%3};"
        : "+f"(c[0]), "+f"(c[1]), "+f"(c[2]), "+f"(c[3])
        : "r"(a[0]), "r"(a[1]), "r"(a[2]), "r"(a[3]), "r"(b[0]), "r"(b[1]));
}

#define NB_SYNC(id)   asm volatile("bar.sync %0, 512;"   :: "r"(id) : "memory")
#define NB_ARRIVE(id) asm volatile("bar.arrive %0, 512;" :: "r"(id) : "memory")

// ---------------------------------------------------------------------------
// Kernel 1: M = W @ T.  512 threads / 16 warps, warp tile 32m x 32n.
// K-chunk = 80 (26 exact phases instead of 65): per-chunk fixed costs
// (barriers + exposed load latency) cut 2.5x. CVT at staging (r14 numerics).
// Tiles [128][84]; 84 mod 32 = 20 -> frag reads conflict-free.
// ---------------------------------------------------------------------------
#define S1_KC   80
#define S1_STR  84
#define S1_TILE (128 * S1_STR)              // 10752 words
#define S1_SMEM (2 * S1_TILE * 4)           // 86016 B

__global__ void __launch_bounds__(512, 1) stage1_kernel(
        const float* __restrict__ W, const float* __restrict__ T) {
    extern __shared__ float s1[];
    float* Wsm = s1;
    float* Bsm = s1 + S1_TILE;

    const int tid  = threadIdx.x;
    const int lane = tid & 31;
    const int warp = tid >> 5;
    const int gid  = lane >> 2;
    const int tig  = lane & 3;
    const int wm   = warp >> 2;        // 0..3 (m)
    const int wn   = warp & 3;         // 0..3 (n)
    const int colbase = blockIdx.x * 128;

    float acc[2][4][4];
#pragma unroll
    for (int mf = 0; mf < 2; mf++)
#pragma unroll
        for (int nf = 0; nf < 4; nf++)
#pragma unroll
            for (int q = 0; q < 4; q++) acc[mf][nf][q] = 0.0f;

    for (int kk = 0; kk < DTS; kk += S1_KC) {   // 26 chunks
        __syncthreads();
        // W tile [128 m][80 k], tf32 at staging
#pragma unroll
        for (int t = 0; t < 20; t++) {
            int e = tid + 512 * t;              // 10240 elements
            int m = e / S1_KC, k = e % S1_KC;
            Wsm[m * S1_STR + k] =
                __uint_as_float(f2tf32(W[(size_t)m * DTS + kk + k]));
        }
        // T tile transposed [128 n][80 t], global coalesced over n
#pragma unroll
        for (int t = 0; t < 20; t++) {
            int e = tid + 512 * t;
            int tt = e >> 7, n = e & 127;
            Bsm[n * S1_STR + tt] =
                __uint_as_float(f2tf32(T[(size_t)(kk + tt) * NNF + colbase + n]));
        }
        __syncthreads();

#pragma unroll
        for (int ks = 0; ks < 10; ks++) {
            uint32_t breg[4][2];
#pragma unroll
            for (int nf = 0; nf < 4; nf++) {
                int n0 = wn * 32 + nf * 8 + gid;
                breg[nf][0] = __float_as_uint(Bsm[n0 * S1_STR + ks * 8 + tig]);
                breg[nf][1] = __float_as_uint(Bsm[n0 * S1_STR + ks * 8 + tig + 4]);
            }
#pragma unroll
            for (int mf = 0; mf < 2; mf++) {
                int r0 = wm * 32 + mf * 16 + gid;
                uint32_t a[4];
                a[0] = __float_as_uint(Wsm[r0 * S1_STR + ks * 8 + tig]);
                a[1] = __float_as_uint(Wsm[(r0 + 8) * S1_STR + ks * 8 + tig]);
                a[2] = __float_as_uint(Wsm[r0 * S1_STR + ks * 8 + tig + 4]);
                a[3] = __float_as_uint(Wsm[(r0 + 8) * S1_STR + ks * 8 + tig + 4]);
#pragma unroll
                for (int nf = 0; nf < 4; nf++)
                    mma_tf32(acc[mf][nf], a, breg[nf]);
            }
        }
    }

#pragma unroll
    for (int mf = 0; mf < 2; mf++) {
        int r0 = wm * 32 + mf * 16 + gid;
#pragma unroll
        for (int nf = 0; nf < 4; nf++) {
            int c0 = colbase + wn * 32 + nf * 8 + 2 * tig;
            g_M[r0 * NNF + c0]           = __uint_as_float(f2tf32(acc[mf][nf][0]));
            g_M[r0 * NNF + c0 + 1]       = __uint_as_float(f2tf32(acc[mf][nf][1]));
            g_M[(r0 + 8) * NNF + c0]     = __uint_as_float(f2tf32(acc[mf][nf][2]));
            g_M[(r0 + 8) * NNF + c0 + 1] = __uint_as_float(f2tf32(acc[mf][nf][3]));
        }
    }
}

// ---------------------------------------------------------------------------
// Pair table: r -> (i, j), i <= j, i-major
// ---------------------------------------------------------------------------
__global__ void build_pairs_kernel() {
    int i = blockIdx.x, j = threadIdx.x;
    if (j >= i) {
        int r = i * NF - (i * (i - 1)) / 2 + (j - i);
        g_pair[r] = (uint32_t)i | ((uint32_t)j << 16);
    }
    if (i == 0 && j < RPAD - RPAIR) g_pair[RPAIR + j] = 0;
}

// ---------------------------------------------------------------------------
// Pack (round-9 coalesced version): one block per k; smem tile; permuted write.
// ---------------------------------------------------------------------------
#define PACK_SMEM (128 * 129 * 4)   // 66048 B

__global__ void __launch_bounds__(256, 1) pack_kernel() {
    extern __shared__ float tile[];    // [128][129]
    const int k   = blockIdx.x;
    const int tid = threadIdx.x;
    const float* Mk = g_M + (size_t)k * NNF;

#pragma unroll
    for (int e = tid; e < NNF; e += 256) {
        int i = e >> 7, j = e & 127;
        tile[i * 129 + j] = Mk[e];
    }
    __syncthreads();

    for (int r = tid; r < RPAIR; r += 256) {
        uint32_t p = g_pair[r];
        int i = p & 0xFFFF, j = p >> 16;
        float v = tile[i * 129 + j];
        if (i != j) v += tile[j * 129 + i];
        int h  = r >> 6, rr = r & 63;
        int ks = rr >> 3, pos = rr & 7;
        int tg = pos & 3, b = pos >> 2;
        int w = (ks >> 1) * 16 + tg * 4 + 2 * (ks & 1) + b;
        g_B[(size_t)(h * 128 + k) * 64 + w] = __uint_as_float(f2tf32(v));
    }
}

// ---------------------------------------------------------------------------
// Stage 2: warp-specialized (confirmed config, verbatim), 512 threads.
// Warps 0-7: consumers (32z x 64k). Warps 8-15: producers. NRUN=129 halves.
// ---------------------------------------------------------------------------
#define FSTRF 129
#define BSTR  80
#define FSM_WORDS  (128 * FSTRF)          // 16512
#define AH_WORDS   8192
#define BH_WORDS   (128 * BSTR)           // 10240
#define S2_SMEM ((FSM_WORDS + 2 * AH_WORDS + 2 * BH_WORDS) * 4)  // 213504 B

__global__ void __launch_bounds__(512, 1) stage2_kernel(
        const float* __restrict__ feat, float* __restrict__ out) {
    extern __shared__ float sm[];
    float* fsm = sm;
    float* Abuf[2] = { sm + FSM_WORDS, sm + FSM_WORDS + AH_WORDS };
    float* Bbuf[2] = { sm + FSM_WORDS + 2 * AH_WORDS,
                       sm + FSM_WORDS + 2 * AH_WORDS + BH_WORDS };

    const int tid  = threadIdx.x;
    const int lane = tid & 31;
    const int warp = tid >> 5;
    const int gid  = lane >> 2;
    const int tig  = lane & 3;
    const int zbase = blockIdx.x * 128;

    for (int e = tid; e < 128 * 128; e += 512) {
        int z = e >> 7, c = e & 127;
        fsm[z * FSTRF + c] =
            (c == 0) ? 1.0f : feat[(size_t)(zbase + z) * NIN + (c - 1)];
    }
    __syncthreads();

    if (warp >= 8) {
        // ===================== PRODUCER (8 warps) =====================
        const int ptid = tid - 256;
        const int pw   = warp - 8;

        for (int h = 0; h < NRUN; ++h) {
            const int p = h & 1;
            if (h >= 2) NB_SYNC(3 + p);

            {
                float* buf = Bbuf[p];
                const float* src = g_B + (size_t)h * 8192;
#pragma unroll
                for (int t = 0; t < 8; t++) {
                    int cc = ptid + 256 * t;
                    int k = cc >> 4, grp = cc & 15;
                    uint32_t dst = (uint32_t)__cvta_generic_to_shared(buf + k * BSTR + grp * 4);
                    asm volatile("cp.async.cg.shared.global [%0], [%1], 16;"
                                 :: "r"(dst), "l"(src + k * 64 + grp * 4));
                }
                asm volatile("cp.async.commit_group;" ::: "memory");
            }

            {
                float* abuf = Abuf[p];
                const uint32_t* pb = g_pair + h * 64;
#pragma unroll
                for (int step = 0; step < 8; step++) {
                    int g = step * 8 + pw;
                    int mfq = g & 1;
                    int ksq = (g >> 1) & 7;
                    int wmq = g >> 4;
                    uint32_t p0 = __ldg(pb + ksq * 8 + tig);
                    uint32_t p1 = __ldg(pb + ksq * 8 + tig + 4);
                    int i0 = p0 & 0xFFFF, j0 = p0 >> 16;
                    int i1 = p1 & 0xFFFF, j1 = p1 >> 16;
                    const float* fz0 = fsm + (wmq * 32 + mfq * 16 + gid) * FSTRF;
                    const float* fz8 = fz0 + 8 * FSTRF;
                    uint32_t v0 = f2tf32(fz0[i0] * fz0[j0]);
                    uint32_t v1 = f2tf32(fz8[i0] * fz8[j0]);
                    uint32_t v2 = f2tf32(fz0[i1] * fz0[j1]);
                    uint32_t v3 = f2tf32(fz8[i1] * fz8[j1]);
                    uint32_t dst = (uint32_t)__cvta_generic_to_shared(
                        abuf + (size_t)g * 128 + lane * 4);
                    asm volatile("st.shared.v4.b32 [%0], {%1, %2, %3, %4};"
                                 :: "r"(dst), "r"(v0), "r"(v1), "r"(v2), "r"(v3));
                }
            }

            asm volatile("cp.async.wait_group 0;" ::: "memory");
            NB_ARRIVE(1 + p);
        }
    } else {
        // ===================== CONSUMER (8 warps, 32z x 64k) =====================
        const int wm = warp >> 1;
        const int wn = warp & 1;

        float acc[2][8][4];
#pragma unroll
        for (int mf = 0; mf < 2; mf++)
#pragma unroll
            for (int nf = 0; nf < 8; nf++)
#pragma unroll
                for (int q = 0; q < 4; q++) acc[mf][nf][q] = 0.0f;

        for (int h = 0; h < NRUN; ++h) {
            const int p = h & 1;
            NB_SYNC(1 + p);
            const float* abuf = Abuf[p];
            const float* bbuf = Bbuf[p];

#pragma unroll
            for (int klp = 0; klp < 4; klp++) {
                uint32_t a4[4][4];
#pragma unroll
                for (int s = 0; s < 2; s++)
#pragma unroll
                    for (int mf = 0; mf < 2; mf++) {
                        int g = wm * 16 + (2 * klp + s) * 2 + mf;
                        float4 v = *(const float4*)(abuf + (size_t)g * 128 + lane * 4);
                        a4[s * 2 + mf][0] = __float_as_uint(v.x);
                        a4[s * 2 + mf][1] = __float_as_uint(v.y);
                        a4[s * 2 + mf][2] = __float_as_uint(v.z);
                        a4[s * 2 + mf][3] = __float_as_uint(v.w);
                    }
#pragma unroll
                for (int nf = 0; nf < 8; nf++) {
                    int n0 = wn * 64 + nf * 8 + gid;
                    float4 v = *(const float4*)(bbuf + n0 * BSTR + klp * 16 + tig * 4);
                    uint32_t b0[2] = { __float_as_uint(v.x), __float_as_uint(v.y) };
                    uint32_t b1[2] = { __float_as_uint(v.z), __float_as_uint(v.w) };
#pragma unroll
                    for (int mf = 0; mf < 2; mf++) {
                        mma_tf32(acc[mf][nf], a4[0 * 2 + mf], b0);
                        mma_tf32(acc[mf][nf], a4[1 * 2 + mf], b1);
                    }
                }
            }
            NB_ARRIVE(3 + p);
        }

        // Epilogue
#pragma unroll
        for (int mf = 0; mf < 2; mf++) {
            int r0 = wm * 32 + mf * 16 + gid;
#pragma unroll
            for (int nf = 0; nf < 8; nf++) {
                int c0 = wn * 64 + nf * 8 + 2 * tig;
                out[(zbase + r0) * KOUT + c0]         = acc[mf][nf][0];
                out[(zbase + r0) * KOUT + c0 + 1]     = acc[mf][nf][1];
                out[(zbase + r0 + 8) * KOUT + c0]     = acc[mf][nf][2];
                out[(zbase + r0 + 8) * KOUT + c0 + 1] = acc[mf][nf][3];
            }
        }
    }
}

// ---------------------------------------------------------------------------
extern "C" void kernel_launch(void* const* d_in, const int* in_sizes, int n_in,
                              void* d_out, int out_size) {
    const float* feat = nullptr;
    const float* W    = nullptr;
    const float* T    = nullptr;
    for (int i = 0; i < n_in; i++) {
        if      (in_sizes[i] == ZB * NIN)   feat = (const float*)d_in[i];
        else if (in_sizes[i] == KOUT * DTS) W    = (const float*)d_in[i];
        else if (in_sizes[i] == DTS * NNF)  T    = (const float*)d_in[i];
    }
    float* out = (float*)d_out;

    cudaFuncSetAttribute(stage1_kernel,
                         cudaFuncAttributeMaxDynamicSharedMemorySize, S1_SMEM);
    cudaFuncSetAttribute(stage2_kernel,
                         cudaFuncAttributeMaxDynamicSharedMemorySize, S2_SMEM);
    cudaFuncSetAttribute(pack_kernel,
                         cudaFuncAttributeMaxDynamicSharedMemorySize, PACK_SMEM);

    build_pairs_kernel<<<128, 128>>>();
    stage1_kernel<<<128, 512, S1_SMEM>>>(W, T);
    pack_kernel<<<128, 256, PACK_SMEM>>>();
    stage2_kernel<<<128, 512, S2_SMEM>>>(feat, out);
}